// round 6
// baseline (speedup 1.0000x reference)
#include <cuda_runtime.h>
#include <cuda_bf16.h>
#include <mma.h>

namespace wm = nvcuda::wmma;

// ---------------- problem constants ----------------
#define BATCH 64
#define TSTEP 32
#define EMBED 512
#define HID   1024
#define VOCAB 10000
#define FEAT  2048
#define GATES 4096           // 4*HID
#define ROWS  2048           // T*B

// ---------------- GEMM tile config ----------------
#define BM 64
#define BN 128
#define BKT 32
#define LDS 40               // BKT + 8 pad (bf16 elems), multiple of 8
#define LDC 132              // BN + 4 pad (f32 elems), multiple of 4

// ---------------- scratch (device globals; no allocations) ----------------
__device__ __align__(256) __nv_bfloat16 g_feat_hi[BATCH*FEAT],  g_feat_lo[BATCH*FEAT];
__device__ __align__(256) __nv_bfloat16 g_Wih_hi[GATES*EMBED],  g_Wih_lo[GATES*EMBED];
__device__ __align__(256) __nv_bfloat16 g_Whh_hi[GATES*HID],    g_Whh_lo[GATES*HID];
__device__ __align__(256) __nv_bfloat16 g_Wfc_hi[VOCAB*HID],    g_Wfc_lo[VOCAB*HID];
__device__ __align__(256) __nv_bfloat16 g_Wh0_hi[HID*FEAT],     g_Wh0_lo[HID*FEAT];
__device__ __align__(256) __nv_bfloat16 g_Wc0_hi[HID*FEAT],     g_Wc0_lo[HID*FEAT];
__device__ __align__(256) __nv_bfloat16 g_emb_hi[ROWS*EMBED],   g_emb_lo[ROWS*EMBED];
__device__ __align__(256) __nv_bfloat16 g_h_hi[BATCH*HID],      g_h_lo[BATCH*HID];
__device__ __align__(256) __nv_bfloat16 g_Hall_hi[ROWS*HID],    g_Hall_lo[ROWS*HID];
__device__ __align__(256) float g_Xg[(size_t)ROWS*GATES];       // x@Wih^T + (b_ih+b_hh)
__device__ __align__(256) float g_bcomb[GATES];
__device__ __align__(256) float g_c[BATCH*HID];
__device__ __align__(256) float g_part[16*BATCH*HID];           // init split-K partials
__device__ __align__(256) float g_spart[4*BATCH*GATES];         // step split-K partials

// ---------------- smem layout ----------------
struct __align__(16) SmemT {
    union {
        struct {
            __nv_bfloat16 A[2][BM*LDS];   // [hi/lo]
            __nv_bfloat16 B[2][BN*LDS];
        } s;
        float ctile[BM*LDC];
    };
};

// ============================================================
// Split-bf16 GEMM:  C[m,n] = sum_k A[m,k]*W[n,k]   (A:[M,K], W:[N,K], both K-major)
// hi/lo split, 3 MMA products -> ~fp32 accuracy.
// gridDim.z>1 => write raw partials to out + z*M*N (deterministic split-K).
// else epilogue: +bias, optional sigmoid (flags&1).
// ============================================================
__global__ __launch_bounds__(256)
void gemm_bf16split(const __nv_bfloat16* __restrict__ Ahi, const __nv_bfloat16* __restrict__ Alo,
                    const __nv_bfloat16* __restrict__ Bhi, const __nv_bfloat16* __restrict__ Blo,
                    int M, int N, int K, int Kchunk,
                    float* __restrict__ out, const float* __restrict__ bias, int flags)
{
    __shared__ SmemT sm;
    const int tid = threadIdx.x;
    const int m0 = blockIdx.y * BM;
    const int n0 = blockIdx.x * BN;
    const int k0 = blockIdx.z * Kchunk;
    const int warp = tid >> 5;
    const int wm = warp & 1;      // 2 warp-rows  (32 rows each)
    const int wn = warp >> 1;     // 4 warp-cols  (32 cols each)

    wm::fragment<wm::accumulator,16,16,16,float> c[2][2];
#pragma unroll
    for (int i=0;i<2;i++)
#pragma unroll
        for (int j=0;j<2;j++) wm::fill_fragment(c[i][j], 0.0f);

    for (int kt = 0; kt < Kchunk; kt += BKT) {
        // stage A tile: 64 rows x 32 k  (hi+lo), uint2 = 4 bf16
#pragma unroll
        for (int i=0;i<2;i++) {
            int s  = tid + i*256;
            int r  = s >> 3, sg = s & 7;
            size_t g = (size_t)(m0 + r)*K + (k0 + kt + sg*4);
            *reinterpret_cast<uint2*>(&sm.s.A[0][r*LDS + sg*4]) = *reinterpret_cast<const uint2*>(Ahi + g);
            *reinterpret_cast<uint2*>(&sm.s.A[1][r*LDS + sg*4]) = *reinterpret_cast<const uint2*>(Alo + g);
        }
        // stage B tile: 128 rows(n) x 32 k (hi+lo), guard n>=N
#pragma unroll
        for (int i=0;i<4;i++) {
            int s  = tid + i*256;
            int r  = s >> 3, sg = s & 7;
            int n  = n0 + r;
            uint2 vh = make_uint2(0u,0u), vl = make_uint2(0u,0u);
            if (n < N) {
                size_t g = (size_t)n*K + (k0 + kt + sg*4);
                vh = *reinterpret_cast<const uint2*>(Bhi + g);
                vl = *reinterpret_cast<const uint2*>(Blo + g);
            }
            *reinterpret_cast<uint2*>(&sm.s.B[0][r*LDS + sg*4]) = vh;
            *reinterpret_cast<uint2*>(&sm.s.B[1][r*LDS + sg*4]) = vl;
        }
        __syncthreads();

#pragma unroll
        for (int kk=0; kk<BKT; kk+=16) {
            wm::fragment<wm::matrix_a,16,16,16,__nv_bfloat16,wm::row_major> ah[2], al[2];
            wm::fragment<wm::matrix_b,16,16,16,__nv_bfloat16,wm::col_major> bh[2], bl[2];
#pragma unroll
            for (int i=0;i<2;i++) {
                wm::load_matrix_sync(ah[i], &sm.s.A[0][(wm*32+i*16)*LDS + kk], LDS);
                wm::load_matrix_sync(al[i], &sm.s.A[1][(wm*32+i*16)*LDS + kk], LDS);
            }
#pragma unroll
            for (int j=0;j<2;j++) {
                wm::load_matrix_sync(bh[j], &sm.s.B[0][(wn*32+j*16)*LDS + kk], LDS);
                wm::load_matrix_sync(bl[j], &sm.s.B[1][(wn*32+j*16)*LDS + kk], LDS);
            }
#pragma unroll
            for (int i=0;i<2;i++)
#pragma unroll
                for (int j=0;j<2;j++) {
                    wm::mma_sync(c[i][j], ah[i], bh[j], c[i][j]);
                    wm::mma_sync(c[i][j], ah[i], bl[j], c[i][j]);
                    wm::mma_sync(c[i][j], al[i], bh[j], c[i][j]);
                }
        }
        __syncthreads();
    }

    // accumulators -> smem tile
#pragma unroll
    for (int i=0;i<2;i++)
#pragma unroll
        for (int j=0;j<2;j++)
            wm::store_matrix_sync(&sm.ctile[(wm*32+i*16)*LDC + wn*32 + j*16], c[i][j], LDC, wm::mem_row_major);
    __syncthreads();

    const bool partial = (gridDim.z > 1);
    float* obase = partial ? out + (size_t)blockIdx.z * M * N : out;
    for (int s = tid; s < BM*BN; s += 256) {
        int r  = s >> 7;          // /128
        int cc = s & 127;
        int n  = n0 + cc;
        if (n >= N) continue;
        float v = sm.ctile[r*LDC + cc];
        if (!partial) {
            if (bias)      v += bias[n];
            if (flags & 1) v = 1.0f / (1.0f + expf(-v));
        }
        obase[(size_t)(m0 + r)*N + n] = v;
    }
}

// ---------------- small helper kernels ----------------
__global__ void split_f32(const float* __restrict__ x, __nv_bfloat16* __restrict__ hi,
                          __nv_bfloat16* __restrict__ lo, int n)
{
    int i = blockIdx.x*256 + threadIdx.x;
    if (i >= n) return;
    float v = x[i];
    __nv_bfloat16 h = __float2bfloat16(v);
    hi[i] = h;
    lo[i] = __float2bfloat16(v - __bfloat162float(h));
}

__global__ void gather_emb(const int* __restrict__ cap, const float* __restrict__ table,
                           __nv_bfloat16* __restrict__ hi, __nv_bfloat16* __restrict__ lo)
{
    int i = blockIdx.x*256 + threadIdx.x;          // over ROWS*EMBED
    if (i >= ROWS*EMBED) return;
    int r = i >> 9, col = i & 511;                 // EMBED=512
    int t = r >> 6, b = r & 63;                    // row = t*64 + b
    int tok = cap[b*TSTEP + t];
    float v = table[(size_t)tok*EMBED + col];
    __nv_bfloat16 h = __float2bfloat16(v);
    hi[i] = h;
    lo[i] = __float2bfloat16(v - __bfloat162float(h));
}

__global__ void add_bias2(const float* __restrict__ a, const float* __restrict__ b,
                          float* __restrict__ o, int n)
{
    int i = blockIdx.x*256 + threadIdx.x;
    if (i < n) o[i] = a[i] + b[i];
}

// split-K reduce + bias, optional f32 out and/or hi/lo out
__global__ void reduce_epi(const float* __restrict__ part, int KS, int total, int N,
                           const float* __restrict__ bias, float* __restrict__ outf,
                           __nv_bfloat16* __restrict__ ohi, __nv_bfloat16* __restrict__ olo)
{
    int i = blockIdx.x*256 + threadIdx.x;
    if (i >= total) return;
    float v = 0.0f;
    for (int z = 0; z < KS; z++) v += part[(size_t)z*total + i];
    v += bias[i % N];
    if (outf) outf[i] = v;
    if (ohi) {
        __nv_bfloat16 h = __float2bfloat16(v);
        ohi[i] = h;
        olo[i] = __float2bfloat16(v - __bfloat162float(h));
    }
}

// fused: sum split-K partials + pre-biased Xg  ->  LSTM cell  ->  h (hi/lo) + H_all row
__global__ void lstm_cell_k(const float* __restrict__ part, const float* __restrict__ xg,
                            float* __restrict__ c,
                            __nv_bfloat16* __restrict__ hhi, __nv_bfloat16* __restrict__ hlo,
                            __nv_bfloat16* __restrict__ Hhi, __nv_bfloat16* __restrict__ Hlo,
                            int t)
{
    int idx = blockIdx.x*256 + threadIdx.x;        // < BATCH*HID
    if (idx >= BATCH*HID) return;
    int b = idx >> 10, j = idx & 1023;
    int base = b * GATES;
    float gi = xg[base + j];
    float gf = xg[base + HID + j];
    float gg = xg[base + 2*HID + j];
    float go = xg[base + 3*HID + j];
#pragma unroll
    for (int z = 0; z < 4; z++) {
        const float* p = part + (size_t)z*(BATCH*GATES) + base;
        gi += p[j]; gf += p[HID + j]; gg += p[2*HID + j]; go += p[3*HID + j];
    }
    float iv = 1.0f/(1.0f+expf(-gi));
    float fv = 1.0f/(1.0f+expf(-gf));
    float gv = tanhf(gg);
    float ov = 1.0f/(1.0f+expf(-go));
    float cv = fv * c[idx] + iv * gv;
    c[idx] = cv;
    float hv = ov * tanhf(cv);
    __nv_bfloat16 hb = __float2bfloat16(hv);
    __nv_bfloat16 lb = __float2bfloat16(hv - __bfloat162float(hb));
    hhi[idx] = hb; hlo[idx] = lb;
    size_t row = (size_t)(t*BATCH + b);
    Hhi[row*HID + j] = hb;
    Hlo[row*HID + j] = lb;
}

// ---------------- driver ----------------
static __nv_bfloat16* dptr_bf16(const void* sym) { void* p=nullptr; cudaGetSymbolAddress(&p, *(const __nv_bfloat16(*)[1])sym); return (__nv_bfloat16*)p; }

extern "C" void kernel_launch(void* const* d_in, const int* in_sizes, int n_in,
                              void* d_out, int out_size)
{
    const float* features = (const float*)d_in[0];
    const int*   captions = (const int*)  d_in[1];
    const float* embed    = (const float*)d_in[2];
    const float* W_init_h = (const float*)d_in[3];
    const float* b_init_h = (const float*)d_in[4];
    const float* W_init_c = (const float*)d_in[5];
    const float* b_init_c = (const float*)d_in[6];
    const float* W_ih     = (const float*)d_in[7];
    const float* b_ih     = (const float*)d_in[8];
    const float* W_hh     = (const float*)d_in[9];
    const float* b_hh     = (const float*)d_in[10];
    const float* W_fc     = (const float*)d_in[11];
    const float* b_fc     = (const float*)d_in[12];
    float* out = (float*)d_out;

    // resolve device-symbol addresses (host side, capture-safe)
    auto sym = [](const void* s){ void* p=nullptr; cudaGetSymbolAddress(&p, s); return p; };
    __nv_bfloat16 *feat_hi=(__nv_bfloat16*)sym(g_feat_hi), *feat_lo=(__nv_bfloat16*)sym(g_feat_lo);
    __nv_bfloat16 *Wih_hi =(__nv_bfloat16*)sym(g_Wih_hi),  *Wih_lo =(__nv_bfloat16*)sym(g_Wih_lo);
    __nv_bfloat16 *Whh_hi =(__nv_bfloat16*)sym(g_Whh_hi),  *Whh_lo =(__nv_bfloat16*)sym(g_Whh_lo);
    __nv_bfloat16 *Wfc_hi =(__nv_bfloat16*)sym(g_Wfc_hi),  *Wfc_lo =(__nv_bfloat16*)sym(g_Wfc_lo);
    __nv_bfloat16 *Wh0_hi =(__nv_bfloat16*)sym(g_Wh0_hi),  *Wh0_lo =(__nv_bfloat16*)sym(g_Wh0_lo);
    __nv_bfloat16 *Wc0_hi =(__nv_bfloat16*)sym(g_Wc0_hi),  *Wc0_lo =(__nv_bfloat16*)sym(g_Wc0_lo);
    __nv_bfloat16 *emb_hi =(__nv_bfloat16*)sym(g_emb_hi),  *emb_lo =(__nv_bfloat16*)sym(g_emb_lo);
    __nv_bfloat16 *h_hi   =(__nv_bfloat16*)sym(g_h_hi),    *h_lo   =(__nv_bfloat16*)sym(g_h_lo);
    __nv_bfloat16 *Hall_hi=(__nv_bfloat16*)sym(g_Hall_hi), *Hall_lo=(__nv_bfloat16*)sym(g_Hall_lo);
    float *Xg    =(float*)sym(g_Xg);
    float *bcomb =(float*)sym(g_bcomb);
    float *cbuf  =(float*)sym(g_c);
    float *part  =(float*)sym(g_part);
    float *spart =(float*)sym(g_spart);

    // 1) split fp32 operands into hi/lo bf16
    split_f32<<<(BATCH*FEAT+255)/256,256>>>(features, feat_hi, feat_lo, BATCH*FEAT);
    split_f32<<<(HID*FEAT+255)/256,  256>>>(W_init_h, Wh0_hi, Wh0_lo, HID*FEAT);
    split_f32<<<(HID*FEAT+255)/256,  256>>>(W_init_c, Wc0_hi, Wc0_lo, HID*FEAT);
    split_f32<<<(GATES*EMBED+255)/256,256>>>(W_ih, Wih_hi, Wih_lo, GATES*EMBED);
    split_f32<<<(GATES*HID+255)/256, 256>>>(W_hh, Whh_hi, Whh_lo, GATES*HID);
    split_f32<<<(VOCAB*HID+255)/256, 256>>>(W_fc, Wfc_hi, Wfc_lo, VOCAB*HID);
    gather_emb<<<(ROWS*EMBED+255)/256,256>>>(captions, embed, emb_hi, emb_lo);
    add_bias2<<<(GATES+255)/256,256>>>(b_ih, b_hh, bcomb, GATES);

    // 2) h0 = features @ W_init_h^T + b  (split-K=16, deterministic reduce)
    gemm_bf16split<<<dim3(HID/BN, 1, 16), 256>>>(feat_hi, feat_lo, Wh0_hi, Wh0_lo,
                                                 BATCH, HID, FEAT, FEAT/16, part, nullptr, 0);
    reduce_epi<<<(BATCH*HID+255)/256,256>>>(part, 16, BATCH*HID, HID, b_init_h,
                                            nullptr, h_hi, h_lo);
    //    c0
    gemm_bf16split<<<dim3(HID/BN, 1, 16), 256>>>(feat_hi, feat_lo, Wc0_hi, Wc0_lo,
                                                 BATCH, HID, FEAT, FEAT/16, part, nullptr, 0);
    reduce_epi<<<(BATCH*HID+255)/256,256>>>(part, 16, BATCH*HID, HID, b_init_c,
                                            cbuf, nullptr, nullptr);

    // 3) Xg[T*B, 4H] = emb @ W_ih^T + (b_ih + b_hh)   (one big GEMM)
    gemm_bf16split<<<dim3(GATES/BN, ROWS/BM, 1), 256>>>(emb_hi, emb_lo, Wih_hi, Wih_lo,
                                                        ROWS, GATES, EMBED, EMBED, Xg, bcomb, 0);

    // 4) recurrence: 32 x (split-K GEMM h@W_hh^T  +  fused reduce+LSTM cell)
    for (int t = 0; t < TSTEP; t++) {
        gemm_bf16split<<<dim3(GATES/BN, 1, 4), 256>>>(h_hi, h_lo, Whh_hi, Whh_lo,
                                                      BATCH, GATES, HID, HID/4, spart, nullptr, 0);
        lstm_cell_k<<<(BATCH*HID+255)/256,256>>>(spart, Xg + (size_t)t*BATCH*GATES, cbuf,
                                                 h_hi, h_lo, Hall_hi, Hall_lo, t);
    }

    // 5) out[T*B, V] = sigmoid(H_all @ W_fc^T + b_fc)  — row t*64+b matches [T,B,V]
    gemm_bf16split<<<dim3((VOCAB+BN-1)/BN, ROWS/BM, 1), 256>>>(Hall_hi, Hall_lo, Wfc_hi, Wfc_lo,
                                                               ROWS, VOCAB, HID, HID, out, b_fc, 1);
    (void)in_sizes; (void)n_in; (void)out_size;
}